// round 15
// baseline (speedup 1.0000x reference)
#include <cuda_runtime.h>
#include <cstdint>
#include <math_constants.h>

#define BB 2
#define TQ 1024
#define TK 1024
#define DD 64
#define QW 4                 // queries per warp
#define WARPS 4              // 128 threads -> one warp per SMSP
#define THREADS (WARPS * 32)
#define QT (WARPS * QW)      // 16 query rows per block
#define KT 32                // key tile (lane = key)
#define KSPLIT 8
#define KB (TK / KSPLIT)     // 128 keys per block
#define NT (KB / KT)         // 4 tiles
#define NB 2                 // V smem buffers (depth-1 prefetch)
#define NROW (BB * TQ)       // 2048 output rows
#define QGRID (TQ / QT)      // 64

// scratch: unnormalized partials per k-split + arrival counters
__device__ float g_po[KSPLIT][NROW * DD];   // 4 MB
__device__ float g_pl[KSPLIT][NROW];        // 64 KB
__device__ int   g_cnt[BB][QGRID];          // zero-init; self-resetting

__device__ __forceinline__ float tanh_fast(float x) {
    float y;
    asm("tanh.approx.f32 %0, %1;" : "=f"(y) : "f"(x));
    return y;
}

// one query x one float4 dim-chunk of scale-weighted tanh
__device__ __forceinline__ void score4(const float4& qv, const float4& u,
                                       const float4& sc, float& a) {
    a = fmaf(sc.x, tanh_fast(qv.x + u.x), a);
    a = fmaf(sc.y, tanh_fast(qv.y + u.y), a);
    a = fmaf(sc.z, tanh_fast(qv.z + u.z), a);
    a = fmaf(sc.w, tanh_fast(qv.w + u.w), a);
}

__device__ __forceinline__ void cp16(void* dst, const void* src) {
    unsigned d = (unsigned)__cvta_generic_to_shared(dst);
    asm volatile("cp.async.cg.shared.global [%0], [%1], 16;" :: "r"(d), "l"(src));
}
__device__ __forceinline__ void cp_commit() { asm volatile("cp.async.commit_group;"); }
template <int N>
__device__ __forceinline__ void cp_wait() { asm volatile("cp.async.wait_group %0;" :: "n"(N)); }

// V tile as float4 chunks, XOR-swizzled: chunk c of key k at k*16 + (c ^ (k&15)).
__device__ __forceinline__ void prefetch_tile(float4* dst, const float4* V4, int tt, int tid) {
    #pragma unroll
    for (int i = 0; i < 4; i++) {            // 512 chunks / 128 threads
        int id = tid + i * THREADS;
        int k = id >> 4, c = id & 15;
        cp16(&dst[k * 16 + (c ^ (k & 15))], &V4[(size_t)tt * KT * 16 + k * 16 + c]);
    }
    cp_commit();
}

__global__ __launch_bounds__(THREADS, 5)
void addattn_kernel(const float* __restrict__ Q,
                    const float* __restrict__ V,
                    const float* __restrict__ S,
                    float* __restrict__ O) {
    __shared__ __align__(16) float4 v_s[NB][KT * 16];   // 16 KB
    __shared__ __align__(16) float4 q_s[QT * 16];       // 4 KB
    __shared__ __align__(16) float4 sc_s[16];           // 256 B
    __shared__ __align__(16) float  p_s[KT][QT];        // 2 KB  [key][query]
    __shared__ int s_last;

    const int tid  = threadIdx.x;
    const int lane = tid & 31;
    const int warp = tid >> 5;
    const int b    = blockIdx.y;
    const int ks   = blockIdx.z;
    const int q0   = blockIdx.x * QT;

    const float4* Q4 = (const float4*)(Q + ((size_t)b * TQ + q0) * DD);
    q_s[tid]           = Q4[tid];             // QT*16 == 256 == 2*THREADS
    q_s[tid + THREADS] = Q4[tid + THREADS];
    if (tid < 16) sc_s[tid] = ((const float4*)S)[tid];

    const float4* V4 = (const float4*)(V + ((size_t)b * TK + (size_t)ks * KB) * DD);
    prefetch_tile(v_s[0], V4, 0, tid);

    float l0 = 0.f, l1 = 0.f, l2 = 0.f, l3 = 0.f;
    float2 o0 = {0.f, 0.f}, o1 = {0.f, 0.f}, o2 = {0.f, 0.f}, o3 = {0.f, 0.f};
    const int sw   = lane & 15;
    const int c2   = lane >> 1, half = lane & 1;
    const int qa   = warp * QW;

    for (int t = 0; t < NT; ++t) {
        cp_wait<0>();        // tile t complete (only outstanding group)
        __syncthreads();     // visible to all; prior iter's reads of buf (t+1)&1 retired
        if (t + 1 < NT) prefetch_tile(v_s[(t + 1) & 1], V4, t + 1, tid);

        const float4* vb = v_s[t & 1];

        // ---- phase 1: scores for 4 queries, lane = key ----
        float a0 = 0.f, a1 = 0.f, a2 = 0.f, a3 = 0.f;
        #pragma unroll
        for (int c = 0; c < 16; c++) {
            float4 sc = sc_s[c];
            float4 u  = vb[lane * 16 + (c ^ sw)];
            score4(q_s[(qa + 0) * 16 + c], u, sc, a0);
            score4(q_s[(qa + 1) * 16 + c], u, sc, a1);
            score4(q_s[(qa + 2) * 16 + c], u, sc, a2);
            score4(q_s[(qa + 3) * 16 + c], u, sc, a3);
        }
        float p0 = __expf(a0), p1 = __expf(a1), p2 = __expf(a2), p3 = __expf(a3);
        l0 += p0; l1 += p1; l2 += p2; l3 += p3;
        *(float4*)&p_s[lane][qa] = make_float4(p0, p1, p2, p3);
        __syncwarp();        // p_s slices are warp-private

        // ---- phase 3: output accumulation, lane -> dims {2*lane, 2*lane+1} ----
        #pragma unroll
        for (int c = 0; c < 16; c++) {
            const int k0 = 2 * c, k1 = 2 * c + 1;
            float4 pa = *(const float4*)&p_s[k0][qa];
            float4 pc = *(const float4*)&p_s[k1][qa];
            float2 va = ((const float2*)&vb[k0 * 16 + (c2 ^ (k0 & 15))])[half];
            float2 vc = ((const float2*)&vb[k1 * 16 + (c2 ^ (k1 & 15))])[half];
            o0.x = fmaf(pa.x, va.x, o0.x); o0.y = fmaf(pa.x, va.y, o0.y);
            o1.x = fmaf(pa.y, va.x, o1.x); o1.y = fmaf(pa.y, va.y, o1.y);
            o2.x = fmaf(pa.z, va.x, o2.x); o2.y = fmaf(pa.z, va.y, o2.y);
            o3.x = fmaf(pa.w, va.x, o3.x); o3.y = fmaf(pa.w, va.y, o3.y);
            o0.x = fmaf(pc.x, vc.x, o0.x); o0.y = fmaf(pc.x, vc.y, o0.y);
            o1.x = fmaf(pc.y, vc.x, o1.x); o1.y = fmaf(pc.y, vc.y, o1.y);
            o2.x = fmaf(pc.z, vc.x, o2.x); o2.y = fmaf(pc.z, vc.y, o2.y);
            o3.x = fmaf(pc.w, vc.x, o3.x); o3.y = fmaf(pc.w, vc.y, o3.y);
        }
    }

    // ---------- write unnormalized partials ----------
    #pragma unroll
    for (int off = 16; off > 0; off >>= 1) {
        l0 += __shfl_xor_sync(0xffffffffu, l0, off);
        l1 += __shfl_xor_sync(0xffffffffu, l1, off);
        l2 += __shfl_xor_sync(0xffffffffu, l2, off);
        l3 += __shfl_xor_sync(0xffffffffu, l3, off);
    }
    const int row0 = b * TQ + q0 + qa;
    ((float2*)&g_po[ks][(size_t)(row0 + 0) * DD])[lane] = o0;
    ((float2*)&g_po[ks][(size_t)(row0 + 1) * DD])[lane] = o1;
    ((float2*)&g_po[ks][(size_t)(row0 + 2) * DD])[lane] = o2;
    ((float2*)&g_po[ks][(size_t)(row0 + 3) * DD])[lane] = o3;
    if (lane == 0) {
        g_pl[ks][row0 + 0] = l0;
        g_pl[ks][row0 + 1] = l1;
        g_pl[ks][row0 + 2] = l2;
        g_pl[ks][row0 + 3] = l3;
    }

    // ---------- fused combine: single-thread release/acquire handshake ----------
    __syncthreads();                               // block's partial writes hb-before here
    if (tid == 0) {
        __threadfence();                           // release: publish whole block's writes
        int old = atomicAdd(&g_cnt[b][blockIdx.x], 1);
        int last = (old == KSPLIT - 1) ? 1 : 0;
        if (last) __threadfence();                 // acquire: see all other blocks' partials
        s_last = last;
    }
    __syncthreads();                               // propagate visibility block-wide
    if (s_last) {
        // 16 rows x 64 dims = 1024 floats; 128 threads x two float4 each
        #pragma unroll
        for (int i = 0; i < 2; i++) {
            const int id  = tid + i * THREADS;
            const int r   = id >> 4;               // 0..15
            const int d4  = id & 15;               // float4 index 0..15
            const int row = b * TQ + q0 + r;
            float l = 0.f;
            #pragma unroll
            for (int s = 0; s < KSPLIT; s++) l += g_pl[s][row];
            float4 acc = make_float4(0.f, 0.f, 0.f, 0.f);
            #pragma unroll
            for (int s = 0; s < KSPLIT; s++) {
                float4 v = ((const float4*)&g_po[s][(size_t)row * DD])[d4];
                acc.x += v.x; acc.y += v.y; acc.z += v.z; acc.w += v.w;
            }
            const float inv = 1.f / l;
            float4 rr; rr.x = acc.x * inv; rr.y = acc.y * inv;
            rr.z = acc.z * inv; rr.w = acc.w * inv;
            ((float4*)(O + (size_t)row * DD))[d4] = rr;
        }
        if (tid == 0) g_cnt[b][blockIdx.x] = 0;    // reset for next graph replay
    }
}

extern "C" void kernel_launch(void* const* d_in, const int* in_sizes, int n_in,
                              void* d_out, int out_size) {
    const float* Q = (const float*)d_in[0];   // query [B, Tq, D] f32
    const float* V = (const float*)d_in[1];   // value [B, Tk, D] f32
    const float* S = (const float*)d_in[2];   // scale [D] f32
    float* O = (float*)d_out;                 // out   [B, Tq, D] f32
    dim3 grid(QGRID, BB, KSPLIT);             // 64 x 2 x 8 = 1024 blocks
    addattn_kernel<<<grid, THREADS>>>(Q, V, S, O);
}